// round 8
// baseline (speedup 1.0000x reference)
#include <cuda_runtime.h>

// y_pred/y_true [16,3,512,512] f32 -> out [48,4].
// sp=Σp, st=Σt, spt=Σpt per group; tp=spt, tn=N-sp-st+spt, fp=sp-spt, fn=st-spt.
// Balanced grid: 48 groups x 37 blocks = 1776 = 148 SMs x 12 blocks exactly ->
// one perfectly uniform wave (fixes the 6-vs-5 blocks/SM imbalance of grid=768).
// Fused epilogue: last block per group (atomic counter) folds 37 partials in
// fixed order and writes the 4 outputs; counter self-resets for graph replay.

constexpr int GROUPS = 48;
constexpr int N_PER_GROUP = 512 * 512;           // 262144 floats
constexpr int N4_PER_GROUP = N_PER_GROUP / 4;    // 65536 float4
constexpr int BLOCKS_PER_GROUP = 37;
constexpr int THREADS = 128;
constexpr int Q = N4_PER_GROUP / BLOCKS_PER_GROUP;  // 1771
constexpr int R = N4_PER_GROUP % BLOCKS_PER_GROUP;  // 9

__device__ float g_partials[GROUPS * BLOCKS_PER_GROUP * 4];
__device__ unsigned int g_count[GROUPS];   // zero-init at load; self-resetting

__global__ __launch_bounds__(THREADS, 12)
void cm_fused(const float* __restrict__ p_in, const float* __restrict__ t_in,
              float* __restrict__ out) {
    const int group = blockIdx.x / BLOCKS_PER_GROUP;
    const int blk   = blockIdx.x % BLOCKS_PER_GROUP;

    // contiguous float4 range for this block within its group
    const int start4 = blk * Q + (blk < R ? blk : R);
    const int cnt4   = Q + (blk < R ? 1 : 0);
    const long long base4 = (long long)group * N4_PER_GROUP + start4;

    const float4* __restrict__ p4 = (const float4*)p_in + base4;
    const float4* __restrict__ t4 = (const float4*)t_in + base4;

    float sp = 0.f, st = 0.f, spt = 0.f;

    #pragma unroll 4
    for (int i = threadIdx.x; i < cnt4; i += THREADS) {
        float4 p = p4[i];
        float4 t = t4[i];
        sp  += p.x + p.y + p.z + p.w;
        st  += t.x + t.y + t.z + t.w;
        spt += p.x * t.x;
        spt += p.y * t.y;
        spt += p.z * t.z;
        spt += p.w * t.w;
    }

    // intra-warp reduce
    #pragma unroll
    for (int off = 16; off > 0; off >>= 1) {
        sp  += __shfl_xor_sync(0xFFFFFFFFu, sp,  off);
        st  += __shfl_xor_sync(0xFFFFFFFFu, st,  off);
        spt += __shfl_xor_sync(0xFFFFFFFFu, spt, off);
    }

    __shared__ float s_sp[4], s_st[4], s_spt[4];
    __shared__ bool  s_last;
    const int wid = threadIdx.x >> 5;
    const int lid = threadIdx.x & 31;
    if (lid == 0) { s_sp[wid] = sp; s_st[wid] = st; s_spt[wid] = spt; }
    __syncthreads();

    if (threadIdx.x == 0) {
        float bsp = 0.f, bst = 0.f, bspt = 0.f;
        #pragma unroll
        for (int w = 0; w < 4; w++) { bsp += s_sp[w]; bst += s_st[w]; bspt += s_spt[w]; }
        float* dst = &g_partials[(group * BLOCKS_PER_GROUP + blk) * 4];
        dst[0] = bsp; dst[1] = bst; dst[2] = bspt;
        __threadfence();
        unsigned int prev = atomicAdd(&g_count[group], 1u);
        s_last = (prev == BLOCKS_PER_GROUP - 1);
    }
    __syncthreads();

    // winner block folds the group's 37 partials in fixed order (deterministic)
    if (s_last && threadIdx.x == 0) {
        volatile float* parts = &g_partials[group * BLOCKS_PER_GROUP * 4];
        float fsp = 0.f, fst = 0.f, fspt = 0.f;
        #pragma unroll
        for (int b = 0; b < BLOCKS_PER_GROUP; b++) {
            fsp  += parts[b * 4 + 0];
            fst  += parts[b * 4 + 1];
            fspt += parts[b * 4 + 2];
        }
        const float Nf = (float)N_PER_GROUP;
        float* o = out + group * 4;
        o[0] = fspt;                    // tp
        o[1] = Nf - fsp - fst + fspt;   // tn
        o[2] = fsp - fspt;              // fp
        o[3] = fst - fspt;              // fn
        g_count[group] = 0;             // reset for next graph replay
        __threadfence();
    }
}

extern "C" void kernel_launch(void* const* d_in, const int* in_sizes, int n_in,
                              void* d_out, int out_size) {
    const float* y_pred = (const float*)d_in[0];
    const float* y_true = (const float*)d_in[1];
    float* out = (float*)d_out;
    cm_fused<<<GROUPS * BLOCKS_PER_GROUP, THREADS>>>(y_pred, y_true, out);
}